// round 15
// baseline (speedup 1.0000x reference)
#include <cuda_runtime.h>

#define THREADS  256
#define WPB      8          // warps per block; 1 row per warp
#define RPB      8
#define NTERMS   16
#define NBUCKETS 64
#define ROWF     512        // floats per row
#define ROWB     2048       // bytes per row

// Buckets padded to one 128-B L2 line each: [b][0]=sum, [b][1]=cnt.
// Zero at module load; finalizing block restores zeros each launch.
__device__ double   g_acc[NBUCKETS][16];
__device__ unsigned g_ticket;

// C = 255*ln2 + lgamma(256) - 256*ln(2*pi)
#define LOSS_C 867.968103160394f

__device__ __forceinline__ float dot4(float4 a, float4 b) {
    return a.x*b.x + a.y*b.y + a.z*b.z + a.w*b.w;
}
__device__ __forceinline__ unsigned su32(const void* p) {
    return (unsigned)__cvta_generic_to_shared(p);
}
__device__ __forceinline__ void bulk_cp(unsigned sdst, const void* gsrc,
                                        unsigned bytes, unsigned mbar) {
    asm volatile(
        "cp.async.bulk.shared::cluster.global.mbarrier::complete_tx::bytes "
        "[%0], [%1], %2, [%3];"
        :: "r"(sdst), "l"(gsrc), "r"(bytes), "r"(mbar) : "memory");
}
__device__ __forceinline__ void red_add_release_f64(double* p, double v) {
    asm volatile("red.add.release.gpu.global.f64 [%0], %1;"
                 :: "l"(p), "d"(v) : "memory");
}
__device__ __forceinline__ unsigned atom_add_acqrel_u32(unsigned* p, unsigned v) {
    unsigned r;
    asm volatile("atom.add.acq_rel.gpu.global.u32 %0, [%1], %2;"
                 : "=r"(r) : "l"(p), "r"(v) : "memory");
    return r;
}
__device__ __forceinline__ double ld_cg_f64(const double* p) {
    double r;
    asm volatile("ld.global.cg.f64 %0, [%1];" : "=d"(r) : "l"(p) : "memory");
    return r;
}
__device__ __forceinline__ void st_cg_f64(double* p, double v) {
    asm volatile("st.global.cg.f64 [%0], %1;" :: "l"(p), "d"(v) : "memory");
}

__global__ void __launch_bounds__(THREADS)
nll_main(const float* __restrict__ preds,
         const void*  __restrict__ target,
         const float* __restrict__ emb,
         float* __restrict__ out, int out_size, int n, long long vocab)
{
    __shared__ alignas(128) float s_p[RPB][ROWF];     // 16 KB preds
    __shared__ alignas(128) float s_e[RPB][ROWF];     // 16 KB emb
    __shared__ alignas(8) unsigned long long s_mbar[WPB];
    __shared__ float    sh_loss[WPB], sh_cnt[WPB];
    __shared__ unsigned s_tkt;

    int tid  = threadIdx.x;
    int lane = tid & 31;
    int w    = tid >> 5;
    int row  = blockIdx.x * RPB + w;

    // Per-warp mbarriers (count=1). Init then block-sync so the async proxy
    // sees initialized barriers before any bulk copy arrives on them.
    if (tid < WPB) {
        asm volatile("mbarrier.init.shared.b64 [%0], 1;"
                     :: "r"(su32(&s_mbar[tid])) : "memory");
    }
    __syncthreads();

    // ---- inline dtype detection (L2-broadcast of first 32 int64 words).
    // int64 buffer: all in [0,vocab) -> 0. int32 buffer: word i valid only
    // if the odd slot is 0 (p~2e-5); all-32-valid is impossible.
    long long dv = ((const long long*)target)[lane];
    unsigned badm = __ballot_sync(0xffffffffu, dv < 0 || dv >= vocab);
    int flag32 = (badm != 0);

    // ---- zero-LDG data path: both 2-KB rows via cp.async.bulk ----
    unsigned mbar = su32(&s_mbar[w]);
    long long t_l = 1;
    if (lane == 0) {
        int rowc = row < n ? row : 0;
        asm volatile("mbarrier.arrive.expect_tx.shared.b64 _, [%0], %1;"
                     :: "r"(mbar), "r"(2u * ROWB) : "memory");
        // preds row: contiguous, independent of target — issue first
        bulk_cp(su32(&s_p[w][0]), preds + (size_t)rowc * ROWF, ROWB, mbar);
        // target hop, then gathered emb row
        if (row < n) {
            t_l = flag32 ? (long long)((const int*)target)[row]
                         : ((const long long*)target)[row];
        }
        long long tg = (t_l == 1) ? 0 : t_l;   // PAD/OOB: fetch row 0, discard
        bulk_cp(su32(&s_e[w][0]), emb + (size_t)tg * ROWF, ROWB, mbar);
    }
    long long t = __shfl_sync(0xffffffffu, t_l, 0);

    // Wait for both copies (phase 0 each launch; acquire for visibility).
    asm volatile(
        "{\n\t"
        ".reg .pred P;\n"
        "$wl_%=:\n\t"
        "mbarrier.try_wait.parity.acquire.cta.shared::cta.b64 P, [%0], 0, 0x989680;\n\t"
        "@P bra.uni $wd_%=;\n\t"
        "bra.uni $wl_%=;\n"
        "$wd_%=:\n\t"
        "}"
        :: "r"(mbar) : "memory");

    const float4* p4 = reinterpret_cast<const float4*>(&s_p[w][0]) + lane;
    const float4* e4 = reinterpret_cast<const float4*>(&s_e[w][0]) + lane;
    float4 a0 = p4[0], a1 = p4[32], a2 = p4[64], a3 = p4[96];
    float4 b0 = e4[0], b1 = e4[32], b2 = e4[64], b3 = e4[96];

    float ss = dot4(a0,a0) + dot4(a1,a1) + dot4(a2,a2) + dot4(a3,a3);
    float dt = dot4(a0,b0) + dot4(a1,b1) + dot4(a2,b2) + dot4(a3,b3);

    #pragma unroll
    for (int o = 16; o > 0; o >>= 1) {
        ss += __shfl_down_sync(0xffffffffu, ss, o);
        dt += __shfl_down_sync(0xffffffffu, dt, o);
    }

    float loss = 0.0f, cnt = 0.0f;
    if (lane == 0 && t != 1) {   // PAD_ID == 1 (OOB rows carry t==1)
        float z = sqrtf(ss);
        float x = 0.25f * ss;
        // S = sum_j x^j / (j! * (256)_j); x ~ 128 => converged well before j=16.
        float S = 1.0f, term = 1.0f;
        #pragma unroll
        for (int j = 1; j < NTERMS; j++) {
            term *= x * (1.0f / ((float)j * (255.0f + (float)j)));
            S += term;
        }
        loss = logf(S) - z - dt - LOSS_C;
        cnt  = 1.0f;
    }
    if (lane == 0) { sh_loss[w] = loss; sh_cnt[w] = cnt; }
    __syncthreads();

    // ---- block reduce: 2 global reds + 1 ticket per block ----
    if (tid == 0) {
        float L = 0.0f, C = 0.0f;
        #pragma unroll
        for (int i = 0; i < WPB; i++) { L += sh_loss[i]; C += sh_cnt[i]; }
        int b = blockIdx.x & (NBUCKETS - 1);
        red_add_release_f64(&g_acc[b][0], (double)L);
        red_add_release_f64(&g_acc[b][1], (double)C);
        s_tkt = atom_add_acqrel_u32(&g_ticket, 1u);
    }
    __syncthreads();

    // ---- last block finalizes + resets state ----
    if (s_tkt == gridDim.x - 1) {
        double s = 0.0, c = 0.0;
        if (tid < NBUCKETS) {
            s = ld_cg_f64(&g_acc[tid][0]);
            c = ld_cg_f64(&g_acc[tid][1]);
        }
        #pragma unroll
        for (int o = 16; o > 0; o >>= 1) {
            s += __shfl_down_sync(0xffffffffu, s, o);
            c += __shfl_down_sync(0xffffffffu, c, o);
        }
        __shared__ double sh_s[2], sh_c[2];
        if (tid < NBUCKETS && lane == 0) { sh_s[tid >> 5] = s; sh_c[tid >> 5] = c; }
        __syncthreads();
        if (tid == 0) {
            float r = (float)((sh_s[0] + sh_s[1]) / (sh_c[0] + sh_c[1]));
            for (int i = 0; i < out_size; i++) out[i] = r;
            g_ticket = 0u;
        }
        if (tid < NBUCKETS) {
            st_cg_f64(&g_acc[tid][0], 0.0);
            st_cg_f64(&g_acc[tid][1], 0.0);
        }
    }
}

extern "C" void kernel_launch(void* const* d_in, const int* in_sizes, int n_in,
                              void* d_out, int out_size) {
    const float* preds  = (const float*)d_in[0];
    const void*  target = d_in[1];
    const float* emb    = (const float*)d_in[2];
    int n = in_sizes[1];                              // B*S rows
    long long vocab = (long long)(in_sizes[2] / 512); // rows of emb table

    int blocks = (n + RPB - 1) / RPB;
    nll_main<<<blocks, THREADS>>>(preds, target, emb, (float*)d_out,
                                  out_size, n, vocab);
}

// round 17
// speedup vs baseline: 1.1569x; 1.1569x over previous
#include <cuda_runtime.h>

#define THREADS  256
#define WPB      8          // warps per block; 1 row per warp
#define RPB      8
#define NTERMS   16
#define NBUCKETS 64
#define ROWF     512        // floats per row
#define ROWB     2048       // bytes per row

// Buckets padded to one 128-B L2 line each: [b][0]=sum, [b][1]=cnt.
// Zero at module load; finalizing block restores zeros each launch.
__device__ double   g_acc[NBUCKETS][16];
__device__ unsigned g_ticket;

// C = 255*ln2 + lgamma(256) - 256*ln(2*pi)
#define LOSS_C 867.968103160394f

__device__ __forceinline__ float dot4(float4 a, float4 b) {
    return a.x*b.x + a.y*b.y + a.z*b.z + a.w*b.w;
}
__device__ __forceinline__ unsigned su32(const void* p) {
    return (unsigned)__cvta_generic_to_shared(p);
}
// L2 evict_last policy: keep the 32-MB working set resident across graph replays.
__device__ __forceinline__ unsigned long long mk_policy() {
    unsigned long long pol;
    asm("createpolicy.fractional.L2::evict_last.b64 %0, 1.0;" : "=l"(pol));
    return pol;
}
__device__ __forceinline__ float4 ldg_el(const float4* p, unsigned long long pol) {
    float4 v;
    asm volatile("ld.global.nc.L2::cache_hint.v4.f32 {%0,%1,%2,%3}, [%4], %5;"
                 : "=f"(v.x), "=f"(v.y), "=f"(v.z), "=f"(v.w)
                 : "l"(p), "l"(pol));
    return v;
}
__device__ __forceinline__ void bulk_cp_el(unsigned sdst, const void* gsrc,
                                           unsigned bytes, unsigned mbar,
                                           unsigned long long pol) {
    asm volatile(
        "cp.async.bulk.shared::cluster.global.mbarrier::complete_tx::bytes.L2::cache_hint "
        "[%0], [%1], %2, [%3], %4;"
        :: "r"(sdst), "l"(gsrc), "r"(bytes), "r"(mbar), "l"(pol) : "memory");
}
__device__ __forceinline__ void red_add_release_f64(double* p, double v) {
    asm volatile("red.add.release.gpu.global.f64 [%0], %1;"
                 :: "l"(p), "d"(v) : "memory");
}
__device__ __forceinline__ unsigned atom_add_acqrel_u32(unsigned* p, unsigned v) {
    unsigned r;
    asm volatile("atom.add.acq_rel.gpu.global.u32 %0, [%1], %2;"
                 : "=r"(r) : "l"(p), "r"(v) : "memory");
    return r;
}
__device__ __forceinline__ double ld_cg_f64(const double* p) {
    double r;
    asm volatile("ld.global.cg.f64 %0, [%1];" : "=d"(r) : "l"(p) : "memory");
    return r;
}
__device__ __forceinline__ void st_cg_f64(double* p, double v) {
    asm volatile("st.global.cg.f64 [%0], %1;" :: "l"(p), "d"(v) : "memory");
}

__global__ void __launch_bounds__(THREADS)
nll_main(const float* __restrict__ preds,
         const void*  __restrict__ target,
         const float* __restrict__ emb,
         float* __restrict__ out, int out_size, int n, long long vocab)
{
    __shared__ alignas(128) float s_emb[RPB][ROWF];   // 16 KB
    __shared__ alignas(8) unsigned long long s_mbar[WPB];
    __shared__ float    sh_loss[WPB], sh_cnt[WPB];
    __shared__ unsigned s_tkt;

    int tid  = threadIdx.x;
    int lane = tid & 31;
    int w    = tid >> 5;
    int row  = blockIdx.x * RPB + w;
    int rowc = row < n ? row : 0;

    unsigned long long pol = mk_policy();

    // Per-warp mbarriers (count=1). Init then block-sync so the async proxy
    // sees initialized barriers before any bulk copy arrives on them.
    if (tid < WPB) {
        asm volatile("mbarrier.init.shared.b64 [%0], 1;"
                     :: "r"(su32(&s_mbar[tid])) : "memory");
    }
    __syncthreads();

    // ---- inline dtype detection (L2-broadcast of first 32 int64 words).
    // int64 buffer: all in [0,vocab) -> 0. int32 buffer: word i valid only
    // if the odd slot is 0 (p~2e-5); all-32-valid is impossible.
    long long dv = ((const long long*)target)[lane];
    unsigned badm = __ballot_sync(0xffffffffu, dv < 0 || dv >= vocab);
    int flag32 = (badm != 0);

    // ---- warp-autonomous pipeline: emb via ONE bulk copy (evict_last) ----
    unsigned mbar = su32(&s_mbar[w]);
    long long t_l = 1;
    if (lane == 0) {
        if (row < n) {
            t_l = flag32 ? (long long)((const int*)target)[row]
                         : ((const long long*)target)[row];
        }
        long long tg = (t_l == 1) ? 0 : t_l;   // PAD/OOB: fetch row 0, discard
        asm volatile("mbarrier.arrive.expect_tx.shared.b64 _, [%0], %1;"
                     :: "r"(mbar), "r"((unsigned)ROWB) : "memory");
        bulk_cp_el(su32(&s_emb[w][0]), emb + (size_t)tg * ROWF, ROWB, mbar, pol);
    }

    // preds to registers: 4 independent LDG.128/lane with evict_last policy,
    // overlapping the bulk copy.
    const float4* p = reinterpret_cast<const float4*>(preds) + (size_t)rowc * (ROWF/4) + lane;
    float4 a0 = ldg_el(p,      pol);
    float4 a1 = ldg_el(p + 32, pol);
    float4 a2 = ldg_el(p + 64, pol);
    float4 a3 = ldg_el(p + 96, pol);

    long long t = __shfl_sync(0xffffffffu, t_l, 0);

    // Wait for the bulk copy (phase 0 each launch; acquire for visibility).
    asm volatile(
        "{\n\t"
        ".reg .pred P;\n"
        "$wl_%=:\n\t"
        "mbarrier.try_wait.parity.acquire.cta.shared::cta.b64 P, [%0], 0, 0x989680;\n\t"
        "@P bra.uni $wd_%=;\n\t"
        "bra.uni $wl_%=;\n"
        "$wd_%=:\n\t"
        "}"
        :: "r"(mbar) : "memory");

    const float4* e4 = reinterpret_cast<const float4*>(&s_emb[w][0]) + lane;
    float4 b0 = e4[0], b1 = e4[32], b2 = e4[64], b3 = e4[96];

    float ss = dot4(a0,a0) + dot4(a1,a1) + dot4(a2,a2) + dot4(a3,a3);
    float dt = dot4(a0,b0) + dot4(a1,b1) + dot4(a2,b2) + dot4(a3,b3);

    #pragma unroll
    for (int o = 16; o > 0; o >>= 1) {
        ss += __shfl_down_sync(0xffffffffu, ss, o);
        dt += __shfl_down_sync(0xffffffffu, dt, o);
    }

    float loss = 0.0f, cnt = 0.0f;
    if (lane == 0 && t != 1) {   // PAD_ID == 1 (OOB rows carry t==1)
        float z = sqrtf(ss);
        float x = 0.25f * ss;
        // S = sum_j x^j / (j! * (256)_j); x ~ 128 => converged well before j=16.
        float S = 1.0f, term = 1.0f;
        #pragma unroll
        for (int j = 1; j < NTERMS; j++) {
            term *= x * (1.0f / ((float)j * (255.0f + (float)j)));
            S += term;
        }
        loss = logf(S) - z - dt - LOSS_C;
        cnt  = 1.0f;
    }
    if (lane == 0) { sh_loss[w] = loss; sh_cnt[w] = cnt; }
    __syncthreads();

    // ---- block reduce: 2 global reds + 1 ticket per block ----
    if (tid == 0) {
        float L = 0.0f, C = 0.0f;
        #pragma unroll
        for (int i = 0; i < WPB; i++) { L += sh_loss[i]; C += sh_cnt[i]; }
        int b = blockIdx.x & (NBUCKETS - 1);
        red_add_release_f64(&g_acc[b][0], (double)L);
        red_add_release_f64(&g_acc[b][1], (double)C);
        s_tkt = atom_add_acqrel_u32(&g_ticket, 1u);
    }
    __syncthreads();

    // ---- last block finalizes + resets state ----
    if (s_tkt == gridDim.x - 1) {
        double s = 0.0, c = 0.0;
        if (tid < NBUCKETS) {
            s = ld_cg_f64(&g_acc[tid][0]);
            c = ld_cg_f64(&g_acc[tid][1]);
        }
        #pragma unroll
        for (int o = 16; o > 0; o >>= 1) {
            s += __shfl_down_sync(0xffffffffu, s, o);
            c += __shfl_down_sync(0xffffffffu, c, o);
        }
        __shared__ double sh_s[2], sh_c[2];
        if (tid < NBUCKETS && lane == 0) { sh_s[tid >> 5] = s; sh_c[tid >> 5] = c; }
        __syncthreads();
        if (tid == 0) {
            float r = (float)((sh_s[0] + sh_s[1]) / (sh_c[0] + sh_c[1]));
            for (int i = 0; i < out_size; i++) out[i] = r;
            g_ticket = 0u;
        }
        if (tid < NBUCKETS) {
            st_cg_f64(&g_acc[tid][0], 0.0);
            st_cg_f64(&g_acc[tid][1], 0.0);
        }
    }
}

extern "C" void kernel_launch(void* const* d_in, const int* in_sizes, int n_in,
                              void* d_out, int out_size) {
    const float* preds  = (const float*)d_in[0];
    const void*  target = d_in[1];
    const float* emb    = (const float*)d_in[2];
    int n = in_sizes[1];                              // B*S rows
    long long vocab = (long long)(in_sizes[2] / 512); // rows of emb table

    int blocks = (n + RPB - 1) / RPB;
    nll_main<<<blocks, THREADS>>>(preds, target, emb, (float*)d_out,
                                  out_size, n, vocab);
}